// round 14
// baseline (speedup 1.0000x reference)
// R14: R13 mega-kernel + readout FUSED into the cell epilogue (atomicAdd into out_y,
// W_ro L1-hot); g_hist deleted (t=63 writes h_final directly); readout_all/final_copy gone.
#include <cuda_runtime.h>
#include <cuda_fp16.h>
#include <cstdint>
#include <cstddef>

#define TSTEPS 64
#define B_     512
#define NA     4
#define NIN    128
#define NH     512
#define NOUT   10
#define AH     2048      // NA * NH
#define KHA    4096      // h split-2 width: [hi(2048)|lo(2048)]
#define KCW    1536      // comm weight width per agent (j != i)
#define KLW    640       // cell weight width: [Whh 512 | Win 128]
#define NITEMS (128 + (TSTEPS - 1) * 384)   // 24320

// ---------------- device scratch ----------------
__device__ __align__(1024) __half g_CWc[(size_t)NA * NH * KCW];    // comm W per target agent
__device__ __align__(1024) __half g_CWl[(size_t)NA * NH * KLW];    // cell W per agent
__device__ __align__(1024) __half g_xs[(size_t)TSTEPS * B_ * 256]; // x split: [t][b][hi128|lo128]
__device__ __align__(1024) __half g_hA[2][(size_t)B_ * KHA];       // h split, double-buffered
__device__ __align__(1024) float g_connP[2][(size_t)NA * B_ * NH]; // comm split-K partials
__device__ __align__(1024) float g_bias[AH];
__device__ int g_qhead0;
__device__ int g_cflag[TSTEPS][128];     // per-step per-tile comm partial count (->2)
__device__ int g_celldone[TSTEPS][8];    // per-step per-row-block cell tile count (->16)
__device__ int g_mask_mode;

// ---------------- helpers ----------------
__device__ __forceinline__ uint32_t smem_u32(const void* p) {
    uint32_t a;
    asm("{ .reg .u64 t; cvta.to.shared.u64 t, %1; cvt.u32.u64 %0, t; }" : "=r"(a) : "l"(p));
    return a;
}
#define SWZ(x) ((x) ^ (((x) >> 3) & 0x70))

__device__ __forceinline__ void cp16(uint32_t dst, const void* src) {
    asm volatile("cp.async.cg.shared.global [%0], [%1], 16;" :: "r"(dst), "l"(src));
}
#define CP_COMMIT() asm volatile("cp.async.commit_group;" ::: "memory")
#define CP_WAIT1()  asm volatile("cp.async.wait_group 1;" ::: "memory")
#define CP_WAIT0()  asm volatile("cp.async.wait_group 0;" ::: "memory")

__device__ __forceinline__ void ldm_x4(uint32_t addr, uint32_t& r0, uint32_t& r1,
                                       uint32_t& r2, uint32_t& r3) {
    asm volatile("ldmatrix.sync.aligned.m8n8.x4.shared.b16 {%0,%1,%2,%3}, [%4];"
                 : "=r"(r0), "=r"(r1), "=r"(r2), "=r"(r3) : "r"(addr));
}
__device__ __forceinline__ void mma16816h(float* c, const uint32_t* a, uint32_t b0, uint32_t b1) {
    asm volatile("mma.sync.aligned.m16n8k16.row.col.f32.f16.f16.f32 "
                 "{%0,%1,%2,%3}, {%4,%5,%6,%7}, {%8,%9}, {%0,%1,%2,%3};"
                 : "+f"(c[0]), "+f"(c[1]), "+f"(c[2]), "+f"(c[3])
                 : "r"(a[0]), "r"(a[1]), "r"(a[2]), "r"(a[3]), "r"(b0), "r"(b1));
}
__device__ __forceinline__ void spin_until(int* p, int target) {
    while (atomicAdd(p, 0) < target) __nanosleep(32);
}

// ---------------- mask dtype detection ----------------
__global__ void detect_mask_kernel(const unsigned char* __restrict__ m) {
    __shared__ int c1, c2;
    if (threadIdx.x == 0) { c1 = 0; c2 = 0; }
    __syncthreads();
    int l1 = 0, l2 = 0;
    for (int i = threadIdx.x; i < 16384; i += blockDim.x) {
        if (m[4 * i + 1]) l1++;
        if (m[4 * i + 2] | m[4 * i + 3]) l2++;
    }
    atomicAdd(&c1, l1);
    atomicAdd(&c2, l2);
    __syncthreads();
    if (threadIdx.x == 0) g_mask_mode = (c1 > 0) ? 0 : ((c2 > 0) ? 1 : 2);
}

// ---------------- prep ----------------
__global__ void prep_kernel(const float* __restrict__ x,
                            const float* __restrict__ Wc, const void* __restrict__ maskv,
                            const float* __restrict__ Whh, const float* __restrict__ Win,
                            const float* __restrict__ bin, const float* __restrict__ bhh,
                            const float* __restrict__ bro, float* __restrict__ outY) {
    const int mode = g_mask_mode;
    const unsigned char* m8 = (const unsigned char*)maskv;
    const float*         mf = (const float*)maskv;
    const int*           mi = (const int*)maskv;
    const size_t stride = (size_t)blockDim.x * gridDim.x;
    const size_t t0 = (size_t)blockIdx.x * blockDim.x + threadIdx.x;

    for (size_t idx = t0; idx < (size_t)NA * NH * KCW; idx += stride) {
        int k = (int)(idx % KCW);
        int r = (int)(idx / KCW);
        int o = r & (NH - 1);
        int i = r >> 9;
        int jj = k >> 9, h = k & (NH - 1);
        int j = jj + (jj >= i);
        size_t widx = (((size_t)j * NA + i) * NH + h) * NH + o;
        bool msk = (mode == 0) ? (m8[widx] != 0)
                 : (mode == 1) ? (mf[widx] != 0.0f)
                               : (mi[widx] != 0);
        g_CWc[idx] = __float2half(msk ? Wc[widx] * 0.1f : 0.0f);
    }
    for (size_t idx = t0; idx < (size_t)NA * NH * KLW; idx += stride) {
        int k = (int)(idx % KLW);
        int r = (int)(idx / KLW);
        int o = r & (NH - 1);
        int a = r >> 9;
        float w = (k < NH) ? Whh[((size_t)a * NH + o) * NH + k]
                           : Win[((size_t)a * NH + o) * NIN + (k - NH)];
        g_CWl[idx] = __float2half(w);
    }
    for (size_t idx = t0; idx < (size_t)TSTEPS * B_ * NIN; idx += stride) {
        int k = (int)(idx & (NIN - 1));
        size_t tb = idx >> 7;
        float v = x[idx];
        __half hi = __float2half(v);
        __half lo = __float2half(v - __half2float(hi));
        __half* row = g_xs + tb * 256;
        row[k] = hi; row[128 + k] = lo;
    }
    for (size_t idx = t0; idx < (size_t)AH; idx += stride)
        g_bias[idx] = bin[idx] + bhh[idx];
    uint32_t* hA32 = (uint32_t*)g_hA[0];
    for (size_t idx = t0; idx < (size_t)B_ * KHA / 2; idx += stride)
        hA32[idx] = 0u;
    // out_y initialized to broadcast b_ro (fused readout accumulates on top)
    for (size_t idx = t0; idx < (size_t)TSTEPS * B_ * NOUT; idx += stride)
        outY[idx] = bro[idx % NOUT];
    if (t0 == 0) g_qhead0 = 0;
    for (size_t idx = t0; idx < (size_t)TSTEPS * 128; idx += stride)
        ((int*)g_cflag)[idx] = 0;
    for (size_t idx = t0; idx < (size_t)TSTEPS * 8; idx += stride)
        ((int*)g_celldone)[idx] = 0;
}

// ---------------- HMMA machinery: CTA tile 64x128, 8 warps (warp 32x32) ----------------
// stage layout (32KB): A_hi 64x64 @0, A_lo 64x64 @8192 (unused by comm), B 128x64 @16384
#define STAGE 32768
#define SMEM_DYN (3 * STAGE + 1024)

__device__ __forceinline__ void load_dc(uint32_t tiles, int s, int tid,
                                        const __half* aHi, int aHiStride,
                                        const __half* aLo, int aLoStride,
                                        const __half* bRow, int bStride,
                                        int mBase, int nBase, int k0b) {
    uint32_t base = tiles + s * STAGE;
#pragma unroll
    for (int u = 0; u < 2; u++) {
        int i = tid * 2 + u;              // 0..511
        int r = i >> 3, g = i & 7;
        cp16(base + SWZ(r * 128 + g * 16), aHi + (size_t)(mBase + r) * aHiStride + g * 8);
    }
#pragma unroll
    for (int u = 0; u < 2; u++) {
        int i = tid * 2 + u;
        int r = i >> 3, g = i & 7;
        cp16(base + 8192 + SWZ(r * 128 + g * 16), aLo + (size_t)(mBase + r) * aLoStride + g * 8);
    }
#pragma unroll
    for (int u = 0; u < 4; u++) {
        int i = tid * 4 + u;              // 0..1023
        int r = i >> 3, g = i & 7;
        cp16(base + 16384 + SWZ(r * 128 + g * 16), bRow + (size_t)(nBase + r) * bStride + k0b + g * 8);
    }
    CP_COMMIT();
}

__device__ __forceinline__ void load_sc(uint32_t tiles, int s, int tid,
                                        const __half* aHi, int aHiStride,
                                        const __half* bRow, int bStride,
                                        int mBase, int nBase, int k0b) {
    uint32_t base = tiles + s * STAGE;
#pragma unroll
    for (int u = 0; u < 2; u++) {
        int i = tid * 2 + u;
        int r = i >> 3, g = i & 7;
        cp16(base + SWZ(r * 128 + g * 16), aHi + (size_t)(mBase + r) * aHiStride + g * 8);
    }
#pragma unroll
    for (int u = 0; u < 4; u++) {
        int i = tid * 4 + u;
        int r = i >> 3, g = i & 7;
        cp16(base + 16384 + SWZ(r * 128 + g * 16), bRow + (size_t)(nBase + r) * bStride + k0b + g * 8);
    }
    CP_COMMIT();
}

__device__ __forceinline__ void compute_dc(uint32_t st, int wm, int wn, int lane,
                                           float acc[2][4][4]) {
    const uint32_t aHiB = st, aLoB = st + 8192, bB = st + 16384;
#pragma unroll
    for (int ks = 0; ks < 4; ks++) {
        const int kb = ks * 32 + (lane >> 4) * 16;
        uint32_t af[2][4], al[2][4];
#pragma unroll
        for (int mt = 0; mt < 2; mt++) {
            int row = wm + mt * 16 + (lane & 15);
            ldm_x4(aHiB + SWZ(row * 128 + kb), af[mt][0], af[mt][1], af[mt][2], af[mt][3]);
            ldm_x4(aLoB + SWZ(row * 128 + kb), al[mt][0], al[mt][1], al[mt][2], al[mt][3]);
        }
        uint32_t bf[4][2];
#pragma unroll
        for (int ng = 0; ng < 2; ng++) {
            int row = wn + ng * 16 + (lane & 15);
            uint32_t r0, r1, r2, r3;
            ldm_x4(bB + SWZ(row * 128 + kb), r0, r1, r2, r3);
            bf[ng * 2][0] = r0; bf[ng * 2 + 1][0] = r1;
            bf[ng * 2][1] = r2; bf[ng * 2 + 1][1] = r3;
        }
#pragma unroll
        for (int mt = 0; mt < 2; mt++)
#pragma unroll
            for (int nt = 0; nt < 4; nt++) {
                mma16816h(acc[mt][nt], af[mt], bf[nt][0], bf[nt][1]);
                mma16816h(acc[mt][nt], al[mt], bf[nt][0], bf[nt][1]);
            }
    }
}

__device__ __forceinline__ void compute_sc(uint32_t st, int wm, int wn, int lane,
                                           float acc[2][4][4]) {
    const uint32_t aHiB = st, bB = st + 16384;
#pragma unroll
    for (int ks = 0; ks < 4; ks++) {
        const int kb = ks * 32 + (lane >> 4) * 16;
        uint32_t af[2][4];
#pragma unroll
        for (int mt = 0; mt < 2; mt++) {
            int row = wm + mt * 16 + (lane & 15);
            ldm_x4(aHiB + SWZ(row * 128 + kb), af[mt][0], af[mt][1], af[mt][2], af[mt][3]);
        }
        uint32_t bf[4][2];
#pragma unroll
        for (int ng = 0; ng < 2; ng++) {
            int row = wn + ng * 16 + (lane & 15);
            uint32_t r0, r1, r2, r3;
            ldm_x4(bB + SWZ(row * 128 + kb), r0, r1, r2, r3);
            bf[ng * 2][0] = r0; bf[ng * 2 + 1][0] = r1;
            bf[ng * 2][1] = r2; bf[ng * 2 + 1][1] = r3;
        }
#pragma unroll
        for (int mt = 0; mt < 2; mt++)
#pragma unroll
            for (int nt = 0; nt < 4; nt++)
                mma16816h(acc[mt][nt], af[mt], bf[nt][0], bf[nt][1]);
    }
}

// ---------------- persistent mega-kernel (fused epilogue readout) ----------------
__global__ __launch_bounds__(256, 2) void mega_kernel(float* __restrict__ connBase,
                                                      float* __restrict__ outY,
                                                      float* __restrict__ hfOut,
                                                      const float* __restrict__ Wro) {
    extern __shared__ char dsm[];
    __shared__ int s_item;
    uint32_t tiles = (smem_u32(dsm) + 1023) & ~1023u;
    const int tid = threadIdx.x, wid = tid >> 5, lane = tid & 31;
    const int wm = (wid & 1) * 32, wn = (wid >> 1) * 32;

    for (;;) {
        __syncthreads();
        if (tid == 0) s_item = atomicAdd(&g_qhead0, 1);
        __syncthreads();
        const int idx = s_item;
        if (idx >= NITEMS) break;

        int t, q;
        if (idx < 128) { t = 0; q = 256 + idx; }
        else { int r = idx - 128; t = 1 + r / 384; q = r % 384; }

        const __half* hRd = g_hA[t & 1];
        __half* hWr = g_hA[(t & 1) ^ 1];
        const __half* xsT = g_xs + (size_t)t * B_ * 256;

        float acc[2][4][4];
#pragma unroll
        for (int i = 0; i < 2; i++)
#pragma unroll
            for (int j = 0; j < 4; j++)
#pragma unroll
                for (int qq = 0; qq < 4; qq++) acc[i][j][qq] = 0.0f;

        if (q < 256) {
            // ---------------- comm item (t >= 1): hi-only, K=768 per split half ----------------
            const int ks = q & 1, tile = q >> 1;
            const int a = tile >> 5, m = (tile >> 2) & 7, n = tile & 3;
            const int mBase = m * 64, nBase = n * 128;
            const __half* Brow = g_CWc + (size_t)a * NH * KCW;

            if (tid == 0) spin_until(&g_celldone[t - 1][m], 16);
            __syncthreads();
            __threadfence();

            auto srcs = [&](int c, const __half*& hi, int& k0b) {
                int cc = ks * 12 + c;                 // 0..23
                int jj = cc >> 3, r8 = cc & 7;
                int j = jj + (jj >= a);
                hi = hRd + j * 512 + r8 * 64;
                k0b = cc * 64;
            };

            const int C = 12;
            {
                const __half* h0; int kb0; srcs(0, h0, kb0);
                load_sc(tiles, 0, tid, h0, KHA, Brow, KCW, mBase, nBase, kb0);
                const __half* h1; int kb1; srcs(1, h1, kb1);
                load_sc(tiles, 1, tid, h1, KHA, Brow, KCW, mBase, nBase, kb1);
            }
            for (int c = 0; c < C; c++) {
                if (c < C - 1) CP_WAIT1(); else CP_WAIT0();
                __syncthreads();
                compute_sc(tiles + (c % 3) * STAGE, wm, wn, lane, acc);
                if (c + 2 < C) {
                    const __half* hs; int kb; srcs(c + 2, hs, kb);
                    load_sc(tiles, (c + 2) % 3, tid, hs, KHA, Brow, KCW, mBase, nBase, kb);
                }
            }
            float* P = g_connP[ks];
#pragma unroll
            for (int mt = 0; mt < 2; mt++)
#pragma unroll
                for (int nt = 0; nt < 4; nt++) {
                    const int r = mBase + wm + mt * 16 + (lane >> 2);
                    const int col = nBase + wn + nt * 8 + (lane & 3) * 2;
                    *(float2*)(P + ((size_t)a * B_ + r) * NH + col) =
                        make_float2(acc[mt][nt][0], acc[mt][nt][1]);
                    *(float2*)(P + ((size_t)a * B_ + r + 8) * NH + col) =
                        make_float2(acc[mt][nt][2], acc[mt][nt][3]);
                }
            __syncthreads();
            __threadfence();
            if (tid == 0) atomicAdd(&g_cflag[t][tile], 1);
        } else {
            // ---------------- cell item (hi+lo double-chunk, K=1280) ----------------
            const int cidx = q - 256;
            const int a = cidx >> 5, m = (cidx >> 2) & 7, n = cidx & 3;
            const int mBase = m * 64, nBase = n * 128;
            const __half* Brow = g_CWl + (size_t)a * NH * KLW;

            if (t > 0) {
                if (tid == 0) spin_until(&g_celldone[t - 1][m], 16);
                __syncthreads();
                __threadfence();
            }

            auto srcs = [&](int c, const __half*& hi, const __half*& lo, int& hs, int& k0b) {
                if (c < 8) { hi = hRd + a * 512 + c * 64; lo = hi + 2048; hs = KHA; }
                else       { hi = xsT + (c - 8) * 64;     lo = hi + 128;  hs = 256; }
                k0b = c * 64;
            };

            const int C = 10;
            {
                const __half *h0, *l0; int s0, kb0; srcs(0, h0, l0, s0, kb0);
                load_dc(tiles, 0, tid, h0, s0, l0, s0, Brow, KLW, mBase, nBase, kb0);
                const __half *h1, *l1; int s1, kb1; srcs(1, h1, l1, s1, kb1);
                load_dc(tiles, 1, tid, h1, s1, l1, s1, Brow, KLW, mBase, nBase, kb1);
            }
            for (int c = 0; c < C; c++) {
                if (c < C - 1) CP_WAIT1(); else CP_WAIT0();
                __syncthreads();
                compute_dc(tiles + (c % 3) * STAGE, wm, wn, lane, acc);
                if (c + 2 < C) {
                    const __half *hs, *ls; int ss, kb; srcs(c + 2, hs, ls, ss, kb);
                    load_dc(tiles, (c + 2) % 3, tid, hs, ss, ls, ss, Brow, KLW, mBase, nBase, kb);
                }
            }
            if (t > 0) {
                if (tid == 0) spin_until(&g_cflag[t][cidx], 2);
                __syncthreads();
                __threadfence();
            }
            // ---- epilogue: bias + conn + tanh -> hA write + fused readout + (t=63) h_final ----
            float* connT = connBase + (size_t)(t - 1) * NA * B_ * NH;   // valid for t>=1
            const float* P0 = g_connP[0];
            const float* P1 = g_connP[1];
            float yacc[4][NOUT];
#pragma unroll
            for (int rr = 0; rr < 4; rr++)
#pragma unroll
                for (int nn = 0; nn < NOUT; nn++) yacc[rr][nn] = 0.0f;

#pragma unroll
            for (int nt = 0; nt < 4; nt++) {
                const int o = nBase + wn + nt * 8 + (lane & 3) * 2;
                const float2 bias2 = *(const float2*)(g_bias + a * NH + o);
                float2 wv[NOUT];
#pragma unroll
                for (int nn = 0; nn < NOUT; nn++)
                    wv[nn] = __ldg((const float2*)(Wro + (size_t)nn * AH + a * NH + o));
#pragma unroll
                for (int mt = 0; mt < 2; mt++) {
#pragma unroll
                    for (int h2 = 0; h2 < 2; h2++) {
                        const int b = mBase + wm + mt * 16 + (lane >> 2) + h2 * 8;
                        float v0 = acc[mt][nt][h2 * 2 + 0] + bias2.x;
                        float v1 = acc[mt][nt][h2 * 2 + 1] + bias2.y;
                        if (t > 0) {
                            const size_t pidx = ((size_t)a * B_ + b) * NH + o;
                            const float2 c0 = *(const float2*)(P0 + pidx);
                            const float2 c1 = *(const float2*)(P1 + pidx);
                            const float cm0 = c0.x + c1.x, cm1 = c0.y + c1.y;
                            *(float2*)(connT + pidx) = make_float2(cm0, cm1);
                            v0 += cm0; v1 += cm1;
                        }
                        v0 = tanhf(v0); v1 = tanhf(v1);
                        if (t < TSTEPS - 1) {
                            __half hh0 = __float2half(v0), hh1 = __float2half(v1);
                            __half ll0 = __float2half(v0 - __half2float(hh0));
                            __half ll1 = __float2half(v1 - __half2float(hh1));
                            __half* hp = hWr + (size_t)b * KHA + a * NH + o;
                            hp[0] = hh0; hp[1] = hh1;
                            hp[2048] = ll0; hp[2049] = ll1;
                        } else {
                            *(float2*)(hfOut + ((size_t)a * B_ + b) * NH + o) =
                                make_float2(v0, v1);
                        }
                        const int rr = mt * 2 + h2;
#pragma unroll
                        for (int nn = 0; nn < NOUT; nn++)
                            yacc[rr][nn] += v0 * wv[nn].x + v1 * wv[nn].y;
                    }
                }
            }
            // butterfly-reduce over the 4-lane o-group (lane^1, lane^2)
#pragma unroll
            for (int rr = 0; rr < 4; rr++)
#pragma unroll
                for (int nn = 0; nn < NOUT; nn++) {
                    yacc[rr][nn] += __shfl_xor_sync(0xFFFFFFFFu, yacc[rr][nn], 1);
                    yacc[rr][nn] += __shfl_xor_sync(0xFFFFFFFFu, yacc[rr][nn], 2);
                }
            // each lane of the group commits its n-slice: n = (lane&3) + 4*j
            float* outT = outY + (size_t)t * B_ * NOUT;
#pragma unroll
            for (int mt = 0; mt < 2; mt++)
#pragma unroll
                for (int h2 = 0; h2 < 2; h2++) {
                    const int b = mBase + wm + mt * 16 + (lane >> 2) + h2 * 8;
                    const int rr = mt * 2 + h2;
#pragma unroll
                    for (int j = 0; j < 3; j++) {
                        const int nn = (lane & 3) + 4 * j;
                        if (nn < NOUT)
                            atomicAdd(outT + (size_t)b * NOUT + nn, yacc[rr][nn]);
                    }
                }
            __syncthreads();
            __threadfence();
            if (tid == 0) atomicAdd(&g_celldone[t][m], 1);
        }
    }
}

// ---------------- launch ----------------
extern "C" void kernel_launch(void* const* d_in, const int* in_sizes, int n_in,
                              void* d_out, int out_size) {
    const float* x   = (const float*)d_in[0];
    const float* Win = (const float*)d_in[1];
    const float* bin = (const float*)d_in[2];
    const float* Whh = (const float*)d_in[3];
    const float* bhh = (const float*)d_in[4];
    const float* Wc  = (const float*)d_in[5];
    const float* Wro = (const float*)d_in[6];
    const float* bro = (const float*)d_in[7];
    const void*  msk = d_in[8];

    float* out       = (float*)d_out;
    float* out_y     = out;
    float* out_hf    = out + (size_t)TSTEPS * B_ * NOUT;
    float* out_conn  = out_hf + (size_t)NA * B_ * NH;

    cudaFuncSetAttribute(mega_kernel, cudaFuncAttributeMaxDynamicSharedMemorySize, SMEM_DYN);

    detect_mask_kernel<<<1, 256>>>((const unsigned char*)msk);
    prep_kernel<<<2048, 256>>>(x, Wc, msk, Whh, Win, bin, bhh, bro, out_y);
    mega_kernel<<<296, 256, SMEM_DYN>>>(out_conn, out_y, out_hf, Wro);
}

// round 15
// speedup vs baseline: 1.0980x; 1.0980x over previous
// R15: R13 (best: 2479us) + readout as overlapped queue items (8/step, after cell items,
// wait celldone[t][m]) + t=63 epilogue writes h_final directly + wider detect_mask.
// GEMM machinery, numerics, protocol identical to R13. R14's in-epilogue readout reverted.
#include <cuda_runtime.h>
#include <cuda_fp16.h>
#include <cstdint>
#include <cstddef>

#define TSTEPS 64
#define B_     512
#define NA     4
#define NIN    128
#define NH     512
#define NOUT   10
#define AH     2048      // NA * NH
#define KHA    4096      // h split-2 width: [hi(2048)|lo(2048)]
#define KCW    1536      // comm weight width per agent (j != i)
#define KLW    640       // cell weight width: [Whh 512 | Win 128]
#define QSTEP  392       // per-step items (t>=1): 256 comm + 128 cell + 8 readout
#define NITEMS (136 + (TSTEPS - 1) * QSTEP)   // 24832

// ---------------- device scratch ----------------
__device__ __align__(1024) __half g_CWc[(size_t)NA * NH * KCW];    // comm W per target agent
__device__ __align__(1024) __half g_CWl[(size_t)NA * NH * KLW];    // cell W per agent
__device__ __align__(1024) __half g_xs[(size_t)TSTEPS * B_ * 256]; // x split: [t][b][hi128|lo128]
__device__ __align__(1024) __half g_hA[2][(size_t)B_ * KHA];       // h split, double-buffered
__device__ __align__(1024) float g_hist[(size_t)TSTEPS * B_ * AH]; // h history (f32)
__device__ __align__(1024) float g_connP[2][(size_t)NA * B_ * NH]; // comm split-K partials
__device__ __align__(1024) float g_bias[AH];
__device__ int g_qhead0;
__device__ int g_cflag[TSTEPS][128];     // per-step per-tile comm partial count (->2)
__device__ int g_celldone[TSTEPS][8];    // per-step per-row-block cell tile count (->16)
__device__ int g_mask_mode;

// ---------------- helpers ----------------
__device__ __forceinline__ uint32_t smem_u32(const void* p) {
    uint32_t a;
    asm("{ .reg .u64 t; cvta.to.shared.u64 t, %1; cvt.u32.u64 %0, t; }" : "=r"(a) : "l"(p));
    return a;
}
#define SWZ(x) ((x) ^ (((x) >> 3) & 0x70))

__device__ __forceinline__ void cp16(uint32_t dst, const void* src) {
    asm volatile("cp.async.cg.shared.global [%0], [%1], 16;" :: "r"(dst), "l"(src));
}
#define CP_COMMIT() asm volatile("cp.async.commit_group;" ::: "memory")
#define CP_WAIT1()  asm volatile("cp.async.wait_group 1;" ::: "memory")
#define CP_WAIT0()  asm volatile("cp.async.wait_group 0;" ::: "memory")

__device__ __forceinline__ void ldm_x4(uint32_t addr, uint32_t& r0, uint32_t& r1,
                                       uint32_t& r2, uint32_t& r3) {
    asm volatile("ldmatrix.sync.aligned.m8n8.x4.shared.b16 {%0,%1,%2,%3}, [%4];"
                 : "=r"(r0), "=r"(r1), "=r"(r2), "=r"(r3) : "r"(addr));
}
__device__ __forceinline__ void mma16816h(float* c, const uint32_t* a, uint32_t b0, uint32_t b1) {
    asm volatile("mma.sync.aligned.m16n8k16.row.col.f32.f16.f16.f32 "
                 "{%0,%1,%2,%3}, {%4,%5,%6,%7}, {%8,%9}, {%0,%1,%2,%3};"
                 : "+f"(c[0]), "+f"(c[1]), "+f"(c[2]), "+f"(c[3])
                 : "r"(a[0]), "r"(a[1]), "r"(a[2]), "r"(a[3]), "r"(b0), "r"(b1));
}
__device__ __forceinline__ void spin_until(int* p, int target) {
    while (atomicAdd(p, 0) < target) __nanosleep(32);
}

// ---------------- mask dtype detection ----------------
__global__ void detect_mask_kernel(const unsigned char* __restrict__ m) {
    __shared__ int c1, c2;
    if (threadIdx.x == 0) { c1 = 0; c2 = 0; }
    __syncthreads();
    int l1 = 0, l2 = 0;
    for (int i = threadIdx.x; i < 16384; i += blockDim.x) {
        if (m[4 * i + 1]) l1++;
        if (m[4 * i + 2] | m[4 * i + 3]) l2++;
    }
    atomicAdd(&c1, l1);
    atomicAdd(&c2, l2);
    __syncthreads();
    if (threadIdx.x == 0) g_mask_mode = (c1 > 0) ? 0 : ((c2 > 0) ? 1 : 2);
}

// ---------------- prep ----------------
__global__ void prep_kernel(const float* __restrict__ x,
                            const float* __restrict__ Wc, const void* __restrict__ maskv,
                            const float* __restrict__ Whh, const float* __restrict__ Win,
                            const float* __restrict__ bin, const float* __restrict__ bhh) {
    const int mode = g_mask_mode;
    const unsigned char* m8 = (const unsigned char*)maskv;
    const float*         mf = (const float*)maskv;
    const int*           mi = (const int*)maskv;
    const size_t stride = (size_t)blockDim.x * gridDim.x;
    const size_t t0 = (size_t)blockIdx.x * blockDim.x + threadIdx.x;

    for (size_t idx = t0; idx < (size_t)NA * NH * KCW; idx += stride) {
        int k = (int)(idx % KCW);
        int r = (int)(idx / KCW);
        int o = r & (NH - 1);
        int i = r >> 9;
        int jj = k >> 9, h = k & (NH - 1);
        int j = jj + (jj >= i);
        size_t widx = (((size_t)j * NA + i) * NH + h) * NH + o;
        bool msk = (mode == 0) ? (m8[widx] != 0)
                 : (mode == 1) ? (mf[widx] != 0.0f)
                               : (mi[widx] != 0);
        g_CWc[idx] = __float2half(msk ? Wc[widx] * 0.1f : 0.0f);
    }
    for (size_t idx = t0; idx < (size_t)NA * NH * KLW; idx += stride) {
        int k = (int)(idx % KLW);
        int r = (int)(idx / KLW);
        int o = r & (NH - 1);
        int a = r >> 9;
        float w = (k < NH) ? Whh[((size_t)a * NH + o) * NH + k]
                           : Win[((size_t)a * NH + o) * NIN + (k - NH)];
        g_CWl[idx] = __float2half(w);
    }
    for (size_t idx = t0; idx < (size_t)TSTEPS * B_ * NIN; idx += stride) {
        int k = (int)(idx & (NIN - 1));
        size_t tb = idx >> 7;
        float v = x[idx];
        __half hi = __float2half(v);
        __half lo = __float2half(v - __half2float(hi));
        __half* row = g_xs + tb * 256;
        row[k] = hi; row[128 + k] = lo;
    }
    for (size_t idx = t0; idx < (size_t)AH; idx += stride)
        g_bias[idx] = bin[idx] + bhh[idx];
    uint32_t* hA32 = (uint32_t*)g_hA[0];
    for (size_t idx = t0; idx < (size_t)B_ * KHA / 2; idx += stride)
        hA32[idx] = 0u;
    if (t0 == 0) g_qhead0 = 0;
    for (size_t idx = t0; idx < (size_t)TSTEPS * 128; idx += stride)
        ((int*)g_cflag)[idx] = 0;
    for (size_t idx = t0; idx < (size_t)TSTEPS * 8; idx += stride)
        ((int*)g_celldone)[idx] = 0;
}

// ---------------- HMMA machinery: CTA tile 64x128, 8 warps (warp 32x32) ----------------
// stage layout (32KB): A_hi 64x64 @0, A_lo 64x64 @8192 (unused by comm), B 128x64 @16384
#define STAGE 32768
#define SMEM_DYN (3 * STAGE + 1024)

__device__ __forceinline__ void load_dc(uint32_t tiles, int s, int tid,
                                        const __half* aHi, int aHiStride,
                                        const __half* aLo, int aLoStride,
                                        const __half* bRow, int bStride,
                                        int mBase, int nBase, int k0b) {
    uint32_t base = tiles + s * STAGE;
#pragma unroll
    for (int u = 0; u < 2; u++) {
        int i = tid * 2 + u;              // 0..511
        int r = i >> 3, g = i & 7;
        cp16(base + SWZ(r * 128 + g * 16), aHi + (size_t)(mBase + r) * aHiStride + g * 8);
    }
#pragma unroll
    for (int u = 0; u < 2; u++) {
        int i = tid * 2 + u;
        int r = i >> 3, g = i & 7;
        cp16(base + 8192 + SWZ(r * 128 + g * 16), aLo + (size_t)(mBase + r) * aLoStride + g * 8);
    }
#pragma unroll
    for (int u = 0; u < 4; u++) {
        int i = tid * 4 + u;              // 0..1023
        int r = i >> 3, g = i & 7;
        cp16(base + 16384 + SWZ(r * 128 + g * 16), bRow + (size_t)(nBase + r) * bStride + k0b + g * 8);
    }
    CP_COMMIT();
}

__device__ __forceinline__ void load_sc(uint32_t tiles, int s, int tid,
                                        const __half* aHi, int aHiStride,
                                        const __half* bRow, int bStride,
                                        int mBase, int nBase, int k0b) {
    uint32_t base = tiles + s * STAGE;
#pragma unroll
    for (int u = 0; u < 2; u++) {
        int i = tid * 2 + u;
        int r = i >> 3, g = i & 7;
        cp16(base + SWZ(r * 128 + g * 16), aHi + (size_t)(mBase + r) * aHiStride + g * 8);
    }
#pragma unroll
    for (int u = 0; u < 4; u++) {
        int i = tid * 4 + u;
        int r = i >> 3, g = i & 7;
        cp16(base + 16384 + SWZ(r * 128 + g * 16), bRow + (size_t)(nBase + r) * bStride + k0b + g * 8);
    }
    CP_COMMIT();
}

__device__ __forceinline__ void compute_dc(uint32_t st, int wm, int wn, int lane,
                                           float acc[2][4][4]) {
    const uint32_t aHiB = st, aLoB = st + 8192, bB = st + 16384;
#pragma unroll
    for (int ks = 0; ks < 4; ks++) {
        const int kb = ks * 32 + (lane >> 4) * 16;
        uint32_t af[2][4], al[2][4];
#pragma unroll
        for (int mt = 0; mt < 2; mt++) {
            int row = wm + mt * 16 + (lane & 15);
            ldm_x4(aHiB + SWZ(row * 128 + kb), af[mt][0], af[mt][1], af[mt][2], af[mt][3]);
            ldm_x4(aLoB + SWZ(row * 128 + kb), al[mt][0], al[mt][1], al[mt][2], al[mt][3]);
        }
        uint32_t bf[4][2];
#pragma unroll
        for (int ng = 0; ng < 2; ng++) {
            int row = wn + ng * 16 + (lane & 15);
            uint32_t r0, r1, r2, r3;
            ldm_x4(bB + SWZ(row * 128 + kb), r0, r1, r2, r3);
            bf[ng * 2][0] = r0; bf[ng * 2 + 1][0] = r1;
            bf[ng * 2][1] = r2; bf[ng * 2 + 1][1] = r3;
        }
#pragma unroll
        for (int mt = 0; mt < 2; mt++)
#pragma unroll
            for (int nt = 0; nt < 4; nt++) {
                mma16816h(acc[mt][nt], af[mt], bf[nt][0], bf[nt][1]);
                mma16816h(acc[mt][nt], al[mt], bf[nt][0], bf[nt][1]);
            }
    }
}

__device__ __forceinline__ void compute_sc(uint32_t st, int wm, int wn, int lane,
                                           float acc[2][4][4]) {
    const uint32_t aHiB = st, bB = st + 16384;
#pragma unroll
    for (int ks = 0; ks < 4; ks++) {
        const int kb = ks * 32 + (lane >> 4) * 16;
        uint32_t af[2][4];
#pragma unroll
        for (int mt = 0; mt < 2; mt++) {
            int row = wm + mt * 16 + (lane & 15);
            ldm_x4(aHiB + SWZ(row * 128 + kb), af[mt][0], af[mt][1], af[mt][2], af[mt][3]);
        }
        uint32_t bf[4][2];
#pragma unroll
        for (int ng = 0; ng < 2; ng++) {
            int row = wn + ng * 16 + (lane & 15);
            uint32_t r0, r1, r2, r3;
            ldm_x4(bB + SWZ(row * 128 + kb), r0, r1, r2, r3);
            bf[ng * 2][0] = r0; bf[ng * 2 + 1][0] = r1;
            bf[ng * 2][1] = r2; bf[ng * 2 + 1][1] = r3;
        }
#pragma unroll
        for (int mt = 0; mt < 2; mt++)
#pragma unroll
            for (int nt = 0; nt < 4; nt++)
                mma16816h(acc[mt][nt], af[mt], bf[nt][0], bf[nt][1]);
    }
}

// ---------------- persistent mega-kernel ----------------
// per-step q layout: [0,256) comm (t>=1), [256,384) cell, [384,392) readout
// t=0 has only cell + readout (136 items)
__global__ __launch_bounds__(256, 2) void mega_kernel(float* __restrict__ connBase,
                                                      float* __restrict__ outY,
                                                      float* __restrict__ hfOut,
                                                      const float* __restrict__ Wro,
                                                      const float* __restrict__ bro) {
    extern __shared__ char dsm[];
    __shared__ int s_item;
    uint32_t tiles = (smem_u32(dsm) + 1023) & ~1023u;
    const int tid = threadIdx.x, wid = tid >> 5, lane = tid & 31;
    const int wm = (wid & 1) * 32, wn = (wid >> 1) * 32;

    for (;;) {
        __syncthreads();
        if (tid == 0) s_item = atomicAdd(&g_qhead0, 1);
        __syncthreads();
        const int idx = s_item;
        if (idx >= NITEMS) break;

        int t, q;
        if (idx < 136) { t = 0; q = (idx < 128) ? (256 + idx) : (384 + idx - 128); }
        else { int r = idx - 136; t = 1 + r / QSTEP; q = r % QSTEP; }

        const __half* hRd = g_hA[t & 1];
        __half* hWr = g_hA[(t & 1) ^ 1];
        const __half* xsT = g_xs + (size_t)t * B_ * 256;

        if (q >= 384) {
            // ---------------- readout item: rows m*64..m*64+63 of step t ----------------
            const int m = q - 384;
            if (tid == 0) spin_until(&g_celldone[t][m], 16);
            __syncthreads();
            __threadfence();
            const float* hist = g_hist + (size_t)t * B_ * AH;
            float* outT = outY + (size_t)t * B_ * NOUT;
            const int rowBase = m * 64 + wid * 8;
            for (int rr = 0; rr < 8; rr++) {
                const int b = rowBase + rr;
                const float* hrow = hist + (size_t)b * AH;
                float acc[NOUT];
#pragma unroll
                for (int nn = 0; nn < NOUT; nn++) acc[nn] = 0.0f;
#pragma unroll 4
                for (int g = 0; g < 16; g++) {
                    const int k = (g * 32 + lane) * 4;
                    const float4 h4 = *(const float4*)(hrow + k);
#pragma unroll
                    for (int nn = 0; nn < NOUT; nn++) {
                        const float4 wv = __ldg((const float4*)(Wro + (size_t)nn * AH + k));
                        acc[nn] += h4.x * wv.x + h4.y * wv.y + h4.z * wv.z + h4.w * wv.w;
                    }
                }
#pragma unroll
                for (int nn = 0; nn < NOUT; nn++) {
#pragma unroll
                    for (int off = 16; off > 0; off >>= 1)
                        acc[nn] += __shfl_xor_sync(0xFFFFFFFFu, acc[nn], off);
                }
                if (lane < NOUT)
                    outT[(size_t)b * NOUT + lane] = acc[lane] + bro[lane];
            }
            continue;
        }

        float acc[2][4][4];
#pragma unroll
        for (int i = 0; i < 2; i++)
#pragma unroll
            for (int j = 0; j < 4; j++)
#pragma unroll
                for (int qq = 0; qq < 4; qq++) acc[i][j][qq] = 0.0f;

        if (q < 256) {
            // ---------------- comm item (t >= 1): hi-only, K=768 per split half ----------------
            const int ks = q & 1, tile = q >> 1;
            const int a = tile >> 5, m = (tile >> 2) & 7, n = tile & 3;
            const int mBase = m * 64, nBase = n * 128;
            const __half* Brow = g_CWc + (size_t)a * NH * KCW;

            if (tid == 0) spin_until(&g_celldone[t - 1][m], 16);
            __syncthreads();
            __threadfence();

            auto srcs = [&](int c, const __half*& hi, int& k0b) {
                int cc = ks * 12 + c;                 // 0..23
                int jj = cc >> 3, r8 = cc & 7;
                int j = jj + (jj >= a);
                hi = hRd + j * 512 + r8 * 64;
                k0b = cc * 64;
            };

            const int C = 12;
            {
                const __half* h0; int kb0; srcs(0, h0, kb0);
                load_sc(tiles, 0, tid, h0, KHA, Brow, KCW, mBase, nBase, kb0);
                const __half* h1; int kb1; srcs(1, h1, kb1);
                load_sc(tiles, 1, tid, h1, KHA, Brow, KCW, mBase, nBase, kb1);
            }
            for (int c = 0; c < C; c++) {
                if (c < C - 1) CP_WAIT1(); else CP_WAIT0();
                __syncthreads();
                compute_sc(tiles + (c % 3) * STAGE, wm, wn, lane, acc);
                if (c + 2 < C) {
                    const __half* hs; int kb; srcs(c + 2, hs, kb);
                    load_sc(tiles, (c + 2) % 3, tid, hs, KHA, Brow, KCW, mBase, nBase, kb);
                }
            }
            float* P = g_connP[ks];
#pragma unroll
            for (int mt = 0; mt < 2; mt++)
#pragma unroll
                for (int nt = 0; nt < 4; nt++) {
                    const int r = mBase + wm + mt * 16 + (lane >> 2);
                    const int col = nBase + wn + nt * 8 + (lane & 3) * 2;
                    *(float2*)(P + ((size_t)a * B_ + r) * NH + col) =
                        make_float2(acc[mt][nt][0], acc[mt][nt][1]);
                    *(float2*)(P + ((size_t)a * B_ + r + 8) * NH + col) =
                        make_float2(acc[mt][nt][2], acc[mt][nt][3]);
                }
            __syncthreads();
            __threadfence();
            if (tid == 0) atomicAdd(&g_cflag[t][tile], 1);
        } else {
            // ---------------- cell item (hi+lo double-chunk, K=1280) ----------------
            const int cidx = q - 256;
            const int a = cidx >> 5, m = (cidx >> 2) & 7, n = cidx & 3;
            const int mBase = m * 64, nBase = n * 128;
            const __half* Brow = g_CWl + (size_t)a * NH * KLW;

            if (t > 0) {
                if (tid == 0) spin_until(&g_celldone[t - 1][m], 16);
                __syncthreads();
                __threadfence();
            }

            auto srcs = [&](int c, const __half*& hi, const __half*& lo, int& hs, int& k0b) {
                if (c < 8) { hi = hRd + a * 512 + c * 64; lo = hi + 2048; hs = KHA; }
                else       { hi = xsT + (c - 8) * 64;     lo = hi + 128;  hs = 256; }
                k0b = c * 64;
            };

            const int C = 10;
            {
                const __half *h0, *l0; int s0, kb0; srcs(0, h0, l0, s0, kb0);
                load_dc(tiles, 0, tid, h0, s0, l0, s0, Brow, KLW, mBase, nBase, kb0);
                const __half *h1, *l1; int s1, kb1; srcs(1, h1, l1, s1, kb1);
                load_dc(tiles, 1, tid, h1, s1, l1, s1, Brow, KLW, mBase, nBase, kb1);
            }
            for (int c = 0; c < C; c++) {
                if (c < C - 1) CP_WAIT1(); else CP_WAIT0();
                __syncthreads();
                compute_dc(tiles + (c % 3) * STAGE, wm, wn, lane, acc);
                if (c + 2 < C) {
                    const __half *hs, *ls; int ss, kb; srcs(c + 2, hs, ls, ss, kb);
                    load_dc(tiles, (c + 2) % 3, tid, hs, ss, ls, ss, Brow, KLW, mBase, nBase, kb);
                }
            }
            if (t > 0) {
                if (tid == 0) spin_until(&g_cflag[t][cidx], 2);
                __syncthreads();
                __threadfence();
            }
            float* hist = g_hist + (size_t)t * B_ * AH;
            float* connT = connBase + (size_t)(t - 1) * NA * B_ * NH;   // valid for t>=1
            const float* P0 = g_connP[0];
            const float* P1 = g_connP[1];
#pragma unroll
            for (int mt = 0; mt < 2; mt++)
#pragma unroll
                for (int nt = 0; nt < 4; nt++) {
                    const int r0 = mBase + wm + mt * 16 + (lane >> 2);
                    const int o = nBase + wn + nt * 8 + (lane & 3) * 2;
                    const float2 bias2 = *(const float2*)(g_bias + a * NH + o);
#pragma unroll
                    for (int h2 = 0; h2 < 2; h2++) {
                        const int b = r0 + h2 * 8;
                        float v0 = acc[mt][nt][h2 * 2 + 0] + bias2.x;
                        float v1 = acc[mt][nt][h2 * 2 + 1] + bias2.y;
                        if (t > 0) {
                            const size_t pidx = ((size_t)a * B_ + b) * NH + o;
                            const float2 c0 = *(const float2*)(P0 + pidx);
                            const float2 c1 = *(const float2*)(P1 + pidx);
                            const float cm0 = c0.x + c1.x, cm1 = c0.y + c1.y;
                            *(float2*)(connT + pidx) = make_float2(cm0, cm1);
                            v0 += cm0; v1 += cm1;
                        }
                        v0 = tanhf(v0); v1 = tanhf(v1);
                        *(float2*)(hist + (size_t)b * AH + a * NH + o) = make_float2(v0, v1);
                        if (t < TSTEPS - 1) {
                            __half hh0 = __float2half(v0), hh1 = __float2half(v1);
                            __half ll0 = __float2half(v0 - __half2float(hh0));
                            __half ll1 = __float2half(v1 - __half2float(hh1));
                            __half* hp = hWr + (size_t)b * KHA + a * NH + o;
                            hp[0] = hh0; hp[1] = hh1;
                            hp[2048] = ll0; hp[2049] = ll1;
                        } else {
                            *(float2*)(hfOut + ((size_t)a * B_ + b) * NH + o) =
                                make_float2(v0, v1);
                        }
                    }
                }
            __syncthreads();
            __threadfence();
            if (tid == 0) atomicAdd(&g_celldone[t][m], 1);
        }
    }
}

// ---------------- launch ----------------
extern "C" void kernel_launch(void* const* d_in, const int* in_sizes, int n_in,
                              void* d_out, int out_size) {
    const float* x   = (const float*)d_in[0];
    const float* Win = (const float*)d_in[1];
    const float* bin = (const float*)d_in[2];
    const float* Whh = (const float*)d_in[3];
    const float* bhh = (const float*)d_in[4];
    const float* Wc  = (const float*)d_in[5];
    const float* Wro = (const float*)d_in[6];
    const float* bro = (const float*)d_in[7];
    const void*  msk = d_in[8];

    float* out       = (float*)d_out;
    float* out_y     = out;
    float* out_hf    = out + (size_t)TSTEPS * B_ * NOUT;
    float* out_conn  = out_hf + (size_t)NA * B_ * NH;

    cudaFuncSetAttribute(mega_kernel, cudaFuncAttributeMaxDynamicSharedMemorySize, SMEM_DYN);

    detect_mask_kernel<<<1, 1024>>>((const unsigned char*)msk);
    prep_kernel<<<2048, 256>>>(x, Wc, msk, Whh, Win, bin, bhh);
    mega_kernel<<<296, 256, SMEM_DYN>>>(out_conn, out_y, out_hf, Wro, bro);
}

// round 16
// speedup vs baseline: 1.2666x; 1.1536x over previous
// R16: R13 base (best: 2479us) + readout_all register-dieted (h4-first loop order,
// launch_bounds(256,2)) + t=63 epilogue writes h_final directly (final_copy deleted)
// + 1024-thread detect_mask. Mega-kernel GEMM/protocol byte-identical to R13.
#include <cuda_runtime.h>
#include <cuda_fp16.h>
#include <cstdint>
#include <cstddef>

#define TSTEPS 64
#define B_     512
#define NA     4
#define NIN    128
#define NH     512
#define NOUT   10
#define AH     2048      // NA * NH
#define KHA    4096      // h split-2 width: [hi(2048)|lo(2048)]
#define KCW    1536      // comm weight width per agent (j != i)
#define KLW    640       // cell weight width: [Whh 512 | Win 128]
#define NITEMS (128 + (TSTEPS - 1) * 384)   // 24320

// ---------------- device scratch ----------------
__device__ __align__(1024) __half g_CWc[(size_t)NA * NH * KCW];    // comm W per target agent
__device__ __align__(1024) __half g_CWl[(size_t)NA * NH * KLW];    // cell W per agent
__device__ __align__(1024) __half g_xs[(size_t)TSTEPS * B_ * 256]; // x split: [t][b][hi128|lo128]
__device__ __align__(1024) __half g_hA[2][(size_t)B_ * KHA];       // h split, double-buffered
__device__ __align__(1024) float g_hist[(size_t)TSTEPS * B_ * AH]; // h history (f32)
__device__ __align__(1024) float g_connP[2][(size_t)NA * B_ * NH]; // comm split-K partials
__device__ __align__(1024) float g_bias[AH];
__device__ int g_qhead0;
__device__ int g_cflag[TSTEPS][128];     // per-step per-tile comm partial count (->2)
__device__ int g_celldone[TSTEPS][8];    // per-step per-row-block cell tile count (->16)
__device__ int g_mask_mode;

// ---------------- helpers ----------------
__device__ __forceinline__ uint32_t smem_u32(const void* p) {
    uint32_t a;
    asm("{ .reg .u64 t; cvta.to.shared.u64 t, %1; cvt.u32.u64 %0, t; }" : "=r"(a) : "l"(p));
    return a;
}
#define SWZ(x) ((x) ^ (((x) >> 3) & 0x70))

__device__ __forceinline__ void cp16(uint32_t dst, const void* src) {
    asm volatile("cp.async.cg.shared.global [%0], [%1], 16;" :: "r"(dst), "l"(src));
}
#define CP_COMMIT() asm volatile("cp.async.commit_group;" ::: "memory")
#define CP_WAIT1()  asm volatile("cp.async.wait_group 1;" ::: "memory")
#define CP_WAIT0()  asm volatile("cp.async.wait_group 0;" ::: "memory")

__device__ __forceinline__ void ldm_x4(uint32_t addr, uint32_t& r0, uint32_t& r1,
                                       uint32_t& r2, uint32_t& r3) {
    asm volatile("ldmatrix.sync.aligned.m8n8.x4.shared.b16 {%0,%1,%2,%3}, [%4];"
                 : "=r"(r0), "=r"(r1), "=r"(r2), "=r"(r3) : "r"(addr));
}
__device__ __forceinline__ void mma16816h(float* c, const uint32_t* a, uint32_t b0, uint32_t b1) {
    asm volatile("mma.sync.aligned.m16n8k16.row.col.f32.f16.f16.f32 "
                 "{%0,%1,%2,%3}, {%4,%5,%6,%7}, {%8,%9}, {%0,%1,%2,%3};"
                 : "+f"(c[0]), "+f"(c[1]), "+f"(c[2]), "+f"(c[3])
                 : "r"(a[0]), "r"(a[1]), "r"(a[2]), "r"(a[3]), "r"(b0), "r"(b1));
}
__device__ __forceinline__ void spin_until(int* p, int target) {
    while (atomicAdd(p, 0) < target) __nanosleep(32);
}

// ---------------- mask dtype detection ----------------
__global__ void detect_mask_kernel(const unsigned char* __restrict__ m) {
    __shared__ int c1, c2;
    if (threadIdx.x == 0) { c1 = 0; c2 = 0; }
    __syncthreads();
    int l1 = 0, l2 = 0;
    for (int i = threadIdx.x; i < 16384; i += blockDim.x) {
        if (m[4 * i + 1]) l1++;
        if (m[4 * i + 2] | m[4 * i + 3]) l2++;
    }
    atomicAdd(&c1, l1);
    atomicAdd(&c2, l2);
    __syncthreads();
    if (threadIdx.x == 0) g_mask_mode = (c1 > 0) ? 0 : ((c2 > 0) ? 1 : 2);
}

// ---------------- prep ----------------
__global__ void prep_kernel(const float* __restrict__ x,
                            const float* __restrict__ Wc, const void* __restrict__ maskv,
                            const float* __restrict__ Whh, const float* __restrict__ Win,
                            const float* __restrict__ bin, const float* __restrict__ bhh) {
    const int mode = g_mask_mode;
    const unsigned char* m8 = (const unsigned char*)maskv;
    const float*         mf = (const float*)maskv;
    const int*           mi = (const int*)maskv;
    const size_t stride = (size_t)blockDim.x * gridDim.x;
    const size_t t0 = (size_t)blockIdx.x * blockDim.x + threadIdx.x;

    for (size_t idx = t0; idx < (size_t)NA * NH * KCW; idx += stride) {
        int k = (int)(idx % KCW);
        int r = (int)(idx / KCW);
        int o = r & (NH - 1);
        int i = r >> 9;
        int jj = k >> 9, h = k & (NH - 1);
        int j = jj + (jj >= i);
        size_t widx = (((size_t)j * NA + i) * NH + h) * NH + o;
        bool msk = (mode == 0) ? (m8[widx] != 0)
                 : (mode == 1) ? (mf[widx] != 0.0f)
                               : (mi[widx] != 0);
        g_CWc[idx] = __float2half(msk ? Wc[widx] * 0.1f : 0.0f);
    }
    for (size_t idx = t0; idx < (size_t)NA * NH * KLW; idx += stride) {
        int k = (int)(idx % KLW);
        int r = (int)(idx / KLW);
        int o = r & (NH - 1);
        int a = r >> 9;
        float w = (k < NH) ? Whh[((size_t)a * NH + o) * NH + k]
                           : Win[((size_t)a * NH + o) * NIN + (k - NH)];
        g_CWl[idx] = __float2half(w);
    }
    for (size_t idx = t0; idx < (size_t)TSTEPS * B_ * NIN; idx += stride) {
        int k = (int)(idx & (NIN - 1));
        size_t tb = idx >> 7;
        float v = x[idx];
        __half hi = __float2half(v);
        __half lo = __float2half(v - __half2float(hi));
        __half* row = g_xs + tb * 256;
        row[k] = hi; row[128 + k] = lo;
    }
    for (size_t idx = t0; idx < (size_t)AH; idx += stride)
        g_bias[idx] = bin[idx] + bhh[idx];
    uint32_t* hA32 = (uint32_t*)g_hA[0];
    for (size_t idx = t0; idx < (size_t)B_ * KHA / 2; idx += stride)
        hA32[idx] = 0u;
    if (t0 == 0) g_qhead0 = 0;
    for (size_t idx = t0; idx < (size_t)TSTEPS * 128; idx += stride)
        ((int*)g_cflag)[idx] = 0;
    for (size_t idx = t0; idx < (size_t)TSTEPS * 8; idx += stride)
        ((int*)g_celldone)[idx] = 0;
}

// ---------------- HMMA machinery: CTA tile 64x128, 8 warps (warp 32x32) ----------------
// stage layout (32KB): A_hi 64x64 @0, A_lo 64x64 @8192 (unused by comm), B 128x64 @16384
#define STAGE 32768
#define SMEM_DYN (3 * STAGE + 1024)

__device__ __forceinline__ void load_dc(uint32_t tiles, int s, int tid,
                                        const __half* aHi, int aHiStride,
                                        const __half* aLo, int aLoStride,
                                        const __half* bRow, int bStride,
                                        int mBase, int nBase, int k0b) {
    uint32_t base = tiles + s * STAGE;
#pragma unroll
    for (int u = 0; u < 2; u++) {
        int i = tid * 2 + u;              // 0..511
        int r = i >> 3, g = i & 7;
        cp16(base + SWZ(r * 128 + g * 16), aHi + (size_t)(mBase + r) * aHiStride + g * 8);
    }
#pragma unroll
    for (int u = 0; u < 2; u++) {
        int i = tid * 2 + u;
        int r = i >> 3, g = i & 7;
        cp16(base + 8192 + SWZ(r * 128 + g * 16), aLo + (size_t)(mBase + r) * aLoStride + g * 8);
    }
#pragma unroll
    for (int u = 0; u < 4; u++) {
        int i = tid * 4 + u;              // 0..1023
        int r = i >> 3, g = i & 7;
        cp16(base + 16384 + SWZ(r * 128 + g * 16), bRow + (size_t)(nBase + r) * bStride + k0b + g * 8);
    }
    CP_COMMIT();
}

__device__ __forceinline__ void load_sc(uint32_t tiles, int s, int tid,
                                        const __half* aHi, int aHiStride,
                                        const __half* bRow, int bStride,
                                        int mBase, int nBase, int k0b) {
    uint32_t base = tiles + s * STAGE;
#pragma unroll
    for (int u = 0; u < 2; u++) {
        int i = tid * 2 + u;
        int r = i >> 3, g = i & 7;
        cp16(base + SWZ(r * 128 + g * 16), aHi + (size_t)(mBase + r) * aHiStride + g * 8);
    }
#pragma unroll
    for (int u = 0; u < 4; u++) {
        int i = tid * 4 + u;
        int r = i >> 3, g = i & 7;
        cp16(base + 16384 + SWZ(r * 128 + g * 16), bRow + (size_t)(nBase + r) * bStride + k0b + g * 8);
    }
    CP_COMMIT();
}

__device__ __forceinline__ void compute_dc(uint32_t st, int wm, int wn, int lane,
                                           float acc[2][4][4]) {
    const uint32_t aHiB = st, aLoB = st + 8192, bB = st + 16384;
#pragma unroll
    for (int ks = 0; ks < 4; ks++) {
        const int kb = ks * 32 + (lane >> 4) * 16;
        uint32_t af[2][4], al[2][4];
#pragma unroll
        for (int mt = 0; mt < 2; mt++) {
            int row = wm + mt * 16 + (lane & 15);
            ldm_x4(aHiB + SWZ(row * 128 + kb), af[mt][0], af[mt][1], af[mt][2], af[mt][3]);
            ldm_x4(aLoB + SWZ(row * 128 + kb), al[mt][0], al[mt][1], al[mt][2], al[mt][3]);
        }
        uint32_t bf[4][2];
#pragma unroll
        for (int ng = 0; ng < 2; ng++) {
            int row = wn + ng * 16 + (lane & 15);
            uint32_t r0, r1, r2, r3;
            ldm_x4(bB + SWZ(row * 128 + kb), r0, r1, r2, r3);
            bf[ng * 2][0] = r0; bf[ng * 2 + 1][0] = r1;
            bf[ng * 2][1] = r2; bf[ng * 2 + 1][1] = r3;
        }
#pragma unroll
        for (int mt = 0; mt < 2; mt++)
#pragma unroll
            for (int nt = 0; nt < 4; nt++) {
                mma16816h(acc[mt][nt], af[mt], bf[nt][0], bf[nt][1]);
                mma16816h(acc[mt][nt], al[mt], bf[nt][0], bf[nt][1]);
            }
    }
}

__device__ __forceinline__ void compute_sc(uint32_t st, int wm, int wn, int lane,
                                           float acc[2][4][4]) {
    const uint32_t aHiB = st, bB = st + 16384;
#pragma unroll
    for (int ks = 0; ks < 4; ks++) {
        const int kb = ks * 32 + (lane >> 4) * 16;
        uint32_t af[2][4];
#pragma unroll
        for (int mt = 0; mt < 2; mt++) {
            int row = wm + mt * 16 + (lane & 15);
            ldm_x4(aHiB + SWZ(row * 128 + kb), af[mt][0], af[mt][1], af[mt][2], af[mt][3]);
        }
        uint32_t bf[4][2];
#pragma unroll
        for (int ng = 0; ng < 2; ng++) {
            int row = wn + ng * 16 + (lane & 15);
            uint32_t r0, r1, r2, r3;
            ldm_x4(bB + SWZ(row * 128 + kb), r0, r1, r2, r3);
            bf[ng * 2][0] = r0; bf[ng * 2 + 1][0] = r1;
            bf[ng * 2][1] = r2; bf[ng * 2 + 1][1] = r3;
        }
#pragma unroll
        for (int mt = 0; mt < 2; mt++)
#pragma unroll
            for (int nt = 0; nt < 4; nt++)
                mma16816h(acc[mt][nt], af[mt], bf[nt][0], bf[nt][1]);
    }
}

// ---------------- persistent mega-kernel (R13 protocol; comm hi-only) ----------------
__global__ __launch_bounds__(256, 2) void mega_kernel(float* __restrict__ connBase,
                                                      float* __restrict__ hfOut) {
    extern __shared__ char dsm[];
    __shared__ int s_item;
    uint32_t tiles = (smem_u32(dsm) + 1023) & ~1023u;
    const int tid = threadIdx.x, wid = tid >> 5, lane = tid & 31;
    const int wm = (wid & 1) * 32, wn = (wid >> 1) * 32;

    for (;;) {
        __syncthreads();
        if (tid == 0) s_item = atomicAdd(&g_qhead0, 1);
        __syncthreads();
        const int idx = s_item;
        if (idx >= NITEMS) break;

        int t, q;
        if (idx < 128) { t = 0; q = 256 + idx; }
        else { int r = idx - 128; t = 1 + r / 384; q = r % 384; }

        const __half* hRd = g_hA[t & 1];
        __half* hWr = g_hA[(t & 1) ^ 1];
        const __half* xsT = g_xs + (size_t)t * B_ * 256;

        float acc[2][4][4];
#pragma unroll
        for (int i = 0; i < 2; i++)
#pragma unroll
            for (int j = 0; j < 4; j++)
#pragma unroll
                for (int qq = 0; qq < 4; qq++) acc[i][j][qq] = 0.0f;

        if (q < 256) {
            // ---------------- comm item (t >= 1): hi-only, K=768 per split half ----------------
            const int ks = q & 1, tile = q >> 1;
            const int a = tile >> 5, m = (tile >> 2) & 7, n = tile & 3;
            const int mBase = m * 64, nBase = n * 128;
            const __half* Brow = g_CWc + (size_t)a * NH * KCW;

            if (tid == 0) spin_until(&g_celldone[t - 1][m], 16);
            __syncthreads();
            __threadfence();

            auto srcs = [&](int c, const __half*& hi, int& k0b) {
                int cc = ks * 12 + c;                 // 0..23
                int jj = cc >> 3, r8 = cc & 7;
                int j = jj + (jj >= a);
                hi = hRd + j * 512 + r8 * 64;
                k0b = cc * 64;
            };

            const int C = 12;
            {
                const __half* h0; int kb0; srcs(0, h0, kb0);
                load_sc(tiles, 0, tid, h0, KHA, Brow, KCW, mBase, nBase, kb0);
                const __half* h1; int kb1; srcs(1, h1, kb1);
                load_sc(tiles, 1, tid, h1, KHA, Brow, KCW, mBase, nBase, kb1);
            }
            for (int c = 0; c < C; c++) {
                if (c < C - 1) CP_WAIT1(); else CP_WAIT0();
                __syncthreads();
                compute_sc(tiles + (c % 3) * STAGE, wm, wn, lane, acc);
                if (c + 2 < C) {
                    const __half* hs; int kb; srcs(c + 2, hs, kb);
                    load_sc(tiles, (c + 2) % 3, tid, hs, KHA, Brow, KCW, mBase, nBase, kb);
                }
            }
            float* P = g_connP[ks];
#pragma unroll
            for (int mt = 0; mt < 2; mt++)
#pragma unroll
                for (int nt = 0; nt < 4; nt++) {
                    const int r = mBase + wm + mt * 16 + (lane >> 2);
                    const int col = nBase + wn + nt * 8 + (lane & 3) * 2;
                    *(float2*)(P + ((size_t)a * B_ + r) * NH + col) =
                        make_float2(acc[mt][nt][0], acc[mt][nt][1]);
                    *(float2*)(P + ((size_t)a * B_ + r + 8) * NH + col) =
                        make_float2(acc[mt][nt][2], acc[mt][nt][3]);
                }
            __syncthreads();
            __threadfence();
            if (tid == 0) atomicAdd(&g_cflag[t][tile], 1);
        } else {
            // ---------------- cell item (hi+lo double-chunk, K=1280) ----------------
            const int cidx = q - 256;
            const int a = cidx >> 5, m = (cidx >> 2) & 7, n = cidx & 3;
            const int mBase = m * 64, nBase = n * 128;
            const __half* Brow = g_CWl + (size_t)a * NH * KLW;

            if (t > 0) {
                if (tid == 0) spin_until(&g_celldone[t - 1][m], 16);
                __syncthreads();
                __threadfence();
            }

            auto srcs = [&](int c, const __half*& hi, const __half*& lo, int& hs, int& k0b) {
                if (c < 8) { hi = hRd + a * 512 + c * 64; lo = hi + 2048; hs = KHA; }
                else       { hi = xsT + (c - 8) * 64;     lo = hi + 128;  hs = 256; }
                k0b = c * 64;
            };

            const int C = 10;
            {
                const __half *h0, *l0; int s0, kb0; srcs(0, h0, l0, s0, kb0);
                load_dc(tiles, 0, tid, h0, s0, l0, s0, Brow, KLW, mBase, nBase, kb0);
                const __half *h1, *l1; int s1, kb1; srcs(1, h1, l1, s1, kb1);
                load_dc(tiles, 1, tid, h1, s1, l1, s1, Brow, KLW, mBase, nBase, kb1);
            }
            for (int c = 0; c < C; c++) {
                if (c < C - 1) CP_WAIT1(); else CP_WAIT0();
                __syncthreads();
                compute_dc(tiles + (c % 3) * STAGE, wm, wn, lane, acc);
                if (c + 2 < C) {
                    const __half *hs, *ls; int ss, kb; srcs(c + 2, hs, ls, ss, kb);
                    load_dc(tiles, (c + 2) % 3, tid, hs, ss, ls, ss, Brow, KLW, mBase, nBase, kb);
                }
            }
            if (t > 0) {
                if (tid == 0) spin_until(&g_cflag[t][cidx], 2);
                __syncthreads();
                __threadfence();
            }
            float* hist = g_hist + (size_t)t * B_ * AH;
            float* connT = connBase + (size_t)(t - 1) * NA * B_ * NH;   // valid for t>=1
            const float* P0 = g_connP[0];
            const float* P1 = g_connP[1];
#pragma unroll
            for (int mt = 0; mt < 2; mt++)
#pragma unroll
                for (int nt = 0; nt < 4; nt++) {
                    const int r0 = mBase + wm + mt * 16 + (lane >> 2);
                    const int o = nBase + wn + nt * 8 + (lane & 3) * 2;
                    const float2 bias2 = *(const float2*)(g_bias + a * NH + o);
#pragma unroll
                    for (int h2 = 0; h2 < 2; h2++) {
                        const int b = r0 + h2 * 8;
                        float v0 = acc[mt][nt][h2 * 2 + 0] + bias2.x;
                        float v1 = acc[mt][nt][h2 * 2 + 1] + bias2.y;
                        if (t > 0) {
                            const size_t pidx = ((size_t)a * B_ + b) * NH + o;
                            const float2 c0 = *(const float2*)(P0 + pidx);
                            const float2 c1 = *(const float2*)(P1 + pidx);
                            const float cm0 = c0.x + c1.x, cm1 = c0.y + c1.y;
                            *(float2*)(connT + pidx) = make_float2(cm0, cm1);
                            v0 += cm0; v1 += cm1;
                        }
                        v0 = tanhf(v0); v1 = tanhf(v1);
                        *(float2*)(hist + (size_t)b * AH + a * NH + o) = make_float2(v0, v1);
                        if (t < TSTEPS - 1) {
                            __half hh0 = __float2half(v0), hh1 = __float2half(v1);
                            __half ll0 = __float2half(v0 - __half2float(hh0));
                            __half ll1 = __float2half(v1 - __half2float(hh1));
                            __half* hp = hWr + (size_t)b * KHA + a * NH + o;
                            hp[0] = hh0; hp[1] = hh1;
                            hp[2048] = ll0; hp[2049] = ll1;
                        } else {
                            *(float2*)(hfOut + ((size_t)a * B_ + b) * NH + o) =
                                make_float2(v0, v1);
                        }
                    }
                }
            __syncthreads();
            __threadfence();
            if (tid == 0) atomicAdd(&g_celldone[t][m], 1);
        }
    }
}

// ---------------- readout: 4 rows/warp, h4-first loop order (low regs, occ 2) ----------------
__global__ __launch_bounds__(256, 2) void readout_all(const float* __restrict__ Wro,
                                                      const float* __restrict__ bro,
                                                      float* __restrict__ out_y) {
    const int t = blockIdx.y;
    const int warp = threadIdx.x >> 5, lane = threadIdx.x & 31;
    const int rowBase = blockIdx.x * 32 + warp * 4;    // 4 rows per warp
    const float* hbase = g_hist + ((size_t)t * B_ + rowBase) * AH;

    float acc[4][NOUT];
#pragma unroll
    for (int r = 0; r < 4; r++)
#pragma unroll
        for (int n = 0; n < NOUT; n++) acc[r][n] = 0.0f;

#pragma unroll 2
    for (int w = 0; w < 16; w++) {
        const int k = w * 128 + lane * 4;
        float4 h4[4];
#pragma unroll
        for (int r = 0; r < 4; r++)
            h4[r] = *(const float4*)(hbase + (size_t)r * AH + k);
#pragma unroll
        for (int n = 0; n < NOUT; n++) {
            const float4 wv = __ldg((const float4*)(Wro + (size_t)n * AH + k));
#pragma unroll
            for (int r = 0; r < 4; r++)
                acc[r][n] += h4[r].x * wv.x + h4[r].y * wv.y + h4[r].z * wv.z + h4[r].w * wv.w;
        }
    }
#pragma unroll
    for (int r = 0; r < 4; r++) {
#pragma unroll
        for (int n = 0; n < NOUT; n++) {
#pragma unroll
            for (int off = 16; off > 0; off >>= 1)
                acc[r][n] += __shfl_xor_sync(0xFFFFFFFFu, acc[r][n], off);
        }
        if (lane < NOUT)
            out_y[((size_t)t * B_ + rowBase + r) * NOUT + lane] = acc[r][lane] + bro[lane];
    }
}

// ---------------- launch ----------------
extern "C" void kernel_launch(void* const* d_in, const int* in_sizes, int n_in,
                              void* d_out, int out_size) {
    const float* x   = (const float*)d_in[0];
    const float* Win = (const float*)d_in[1];
    const float* bin = (const float*)d_in[2];
    const float* Whh = (const float*)d_in[3];
    const float* bhh = (const float*)d_in[4];
    const float* Wc  = (const float*)d_in[5];
    const float* Wro = (const float*)d_in[6];
    const float* bro = (const float*)d_in[7];
    const void*  msk = d_in[8];

    float* out       = (float*)d_out;
    float* out_y     = out;
    float* out_hf    = out + (size_t)TSTEPS * B_ * NOUT;
    float* out_conn  = out_hf + (size_t)NA * B_ * NH;

    cudaFuncSetAttribute(mega_kernel, cudaFuncAttributeMaxDynamicSharedMemorySize, SMEM_DYN);

    detect_mask_kernel<<<1, 1024>>>((const unsigned char*)msk);
    prep_kernel<<<2048, 256>>>(x, Wc, msk, Whh, Win, bin, bhh);
    mega_kernel<<<296, 256, SMEM_DYN>>>(out_conn, out_hf);
    readout_all<<<dim3(16, TSTEPS), 256>>>(Wro, bro, out_y);
}